// round 15
// baseline (speedup 1.0000x reference)
#include <cuda_runtime.h>
#include <cuda_fp16.h>
#include <cstdint>

#define DDIM 128
#define MAXN 50048
#define MAXE 2097152
#define PADB2 132   // Bs row stride (half2 words), rows indexed by k/2
#define PADAH 136   // As row stride (halfs) -> conflict-free fragment LDS
#define TILE_M 64

// Scratch (allocation-free: __device__ globals). Half buffers alias floats.
__device__ float g_b0[(size_t)MAXN * DDIM / 2];   // xh ping
__device__ float g_b1[(size_t)MAXN * DDIM / 2];   // xh pong
__device__ float g_b2[(size_t)MAXN * DDIM / 2];   // aggh
__device__ float g_b3[(size_t)MAXN * DDIM / 2];   // hh
__device__ int   g_cnt[MAXN];
__device__ int   g_rowptr[MAXN + 1];
__device__ int   g_cursor[MAXN];
__device__ int   g_esrc[MAXE];

// ---------------------------------------------------------------------------
// Helpers
// ---------------------------------------------------------------------------
__device__ __forceinline__ uint32_t smem_u32(const void* p) {
    uint32_t a;
    asm("{ .reg .u64 t; cvta.to.shared.u64 t, %1; cvt.u32.u64 %0, t; }"
        : "=r"(a) : "l"(p));
    return a;
}
__device__ __forceinline__ void cp_async16(uint32_t dst, const void* src, bool pred) {
    int sz = pred ? 16 : 0;
    asm volatile("cp.async.ca.shared.global [%0], [%1], 16, %2;"
                 :: "r"(dst), "l"(src), "r"(sz));
}
__device__ __forceinline__ void cp_commit() {
    asm volatile("cp.async.commit_group;" ::: "memory");
}
__device__ __forceinline__ uint32_t pack_h2(float lo, float hi) {
    __half2 h = __floats2half2_rn(lo, hi);
    return *(uint32_t*)&h;
}
__device__ __forceinline__ void mma_m16n8k16_f16(float c[4], const uint32_t a[4],
                                                 const uint32_t b[2]) {
    asm volatile(
        "mma.sync.aligned.m16n8k16.row.col.f32.f16.f16.f32 "
        "{%0,%1,%2,%3}, {%4,%5,%6,%7}, {%8,%9}, {%0,%1,%2,%3};\n"
        : "+f"(c[0]), "+f"(c[1]), "+f"(c[2]), "+f"(c[3])
        : "r"(a[0]), "r"(a[1]), "r"(a[2]), "r"(a[3]), "r"(b[0]), "r"(b[1]));
}
__device__ __forceinline__ void store2(float* C, size_t idx, float x, float y) {
    float2 o; o.x = x; o.y = y;
    *(float2*)(C + idx) = o;
}
__device__ __forceinline__ void store2(__half* C, size_t idx, float x, float y) {
    *(uint32_t*)(C + idx) = pack_h2(x, y);
}

// Per-dtype row payload for the gather (4 values per lane).
template <typename T> struct RowVec;
template <> struct RowVec<__half> {
    using V = uint2;
    static __device__ __forceinline__ V zero() { return make_uint2(0u, 0u); }
    static __device__ __forceinline__ void add(float& a0, float& a1, float& a2,
                                               float& a3, V v) {
        float2 p0 = __half22float2(*(__half2*)&v.x);
        float2 p1 = __half22float2(*(__half2*)&v.y);
        a0 += p0.x; a1 += p0.y; a2 += p1.x; a3 += p1.y;
    }
};
template <> struct RowVec<float> {
    using V = float4;
    static __device__ __forceinline__ V zero() { return make_float4(0.f, 0.f, 0.f, 0.f); }
    static __device__ __forceinline__ void add(float& a0, float& a1, float& a2,
                                               float& a3, V v) {
        a0 += v.x; a1 += v.y; a2 += v.z; a3 += v.w;
    }
};

// ---------------------------------------------------------------------------
// Edge dtype self-detection (int64 vs int32). When int64, indices fit in the
// low 32-bit word (N < 2^31) -> narrow loads halve edge traffic.
// ---------------------------------------------------------------------------
__device__ __forceinline__ bool edges_are_i64(const void* ei, int N) {
    const long long* e64 = (const long long*)ei;
#pragma unroll
    for (int i = 0; i < 4; i++) {
        long long v = e64[i];
        if (v < 0 || v >= (long long)N) return false;
    }
    return true;
}

__global__ void zero_cnt_kernel(int* cnt, int n) {
    int i = blockIdx.x * blockDim.x + threadIdx.x;
    if (i < n) cnt[i] = 0;
}

__global__ void hist_kernel(int* cnt, const void* ei, int E, int N) {
    int i = blockIdx.x * blockDim.x + threadIdx.x;
    if (i >= E) return;
    bool is64 = edges_are_i64(ei, N);
    const int* e32 = (const int*)ei;
    int d = is64 ? e32[2 * ((size_t)E + i)] : e32[E + i];
    atomicAdd(&cnt[d], 1);
}

__global__ void scan_kernel(const int* __restrict__ cnt, int* __restrict__ rowptr,
                            int* __restrict__ cursor, int N) {
    __shared__ int part[1024];
    int tid = threadIdx.x;
    int chunk = (N + 1023) / 1024;
    int start = tid * chunk;
    int end = min(start + chunk, N);
    int s = 0;
    for (int i = start; i < end; i++) s += cnt[i];
    part[tid] = s;
    __syncthreads();
    for (int off = 1; off < 1024; off <<= 1) {
        int v = (tid >= off) ? part[tid - off] : 0;
        __syncthreads();
        part[tid] += v;
        __syncthreads();
    }
    int run = (tid == 0) ? 0 : part[tid - 1];
    for (int i = start; i < end; i++) {
        rowptr[i] = run;
        cursor[i] = run;
        run += cnt[i];
    }
    if (end == N) rowptr[N] = run;
}

__global__ void bucket_kernel(int* __restrict__ cursor, int* __restrict__ esrc,
                              const void* ei, int E, int N) {
    int i = blockIdx.x * blockDim.x + threadIdx.x;
    if (i >= E) return;
    bool is64 = edges_are_i64(ei, N);
    const int* e32 = (const int*)ei;
    int s, d;
    if (is64) {
        s = e32[2 * (size_t)i];
        d = e32[2 * ((size_t)E + i)];
    } else {
        s = e32[i];
        d = e32[E + i];
    }
    int pos = atomicAdd(&cursor[d], 1);
    esrc[pos] = s;
}

// ---------------------------------------------------------------------------
// aggh[i] = fp16( x[i] + sum_{s in in-nb(i)} x[s] )  (fp32 accum).
// One warp per node; MLP-8 batched neighbor row prefetch. T = __half or float.
// ---------------------------------------------------------------------------
template <typename T>
__global__ void gather_agg_f16(__half* __restrict__ agg, const T* __restrict__ x,
                               const int* __restrict__ rowptr,
                               const int* __restrict__ esrc, int N) {
    using RV = RowVec<T>;
    using V = typename RV::V;
    int node = blockIdx.x * (blockDim.x >> 5) + (threadIdx.x >> 5);
    if (node >= N) return;
    int lane = threadIdx.x & 31;

    float acc0 = 0.f, acc1 = 0.f, acc2 = 0.f, acc3 = 0.f;
    {
        V u = ((const V*)(x + (size_t)node * DDIM))[lane];
        RV::add(acc0, acc1, acc2, acc3, u);
    }
    int b = rowptr[node];
    int e = rowptr[node + 1];

    for (int base = b; base < e; base += 32) {
        int m = min(32, e - base);
        int sv = (lane < m) ? esrc[base + lane] : 0;
        for (int j0 = 0; j0 < m; j0 += 8) {
            V v[8];
#pragma unroll
            for (int jj = 0; jj < 8; jj++) {
                int s = __shfl_sync(0xffffffffu, sv, (j0 + jj) & 31);
                v[jj] = (j0 + jj < m) ? ((const V*)(x + (size_t)s * DDIM))[lane]
                                      : RV::zero();
            }
#pragma unroll
            for (int jj = 0; jj < 8; jj++)
                RV::add(acc0, acc1, acc2, acc3, v[jj]);
        }
    }
    uint2 o;
    o.x = pack_h2(acc0, acc1);
    o.y = pack_h2(acc2, acc3);
    ((uint2*)(agg + (size_t)node * DDIM))[lane] = o;
}

// ---------------------------------------------------------------------------
// Persistent pipelined FP16 GEMM (m16n8k16, fp32 accum), fp16 A in gmem:
//   C[M,128] = relu(A[M,128] @ W[128,128] + bias)   (C fp16 or fp32)
// TILE_M=64 rows/tile -> 3 CTAs/SM (444 slots for 782 tiles: 88% balance vs
// 66% at M=128). 8 warps, 4(m)x2(n): each warp 16 rows x 64 cols.
// W staged once as k-paired half2. A via cp.async 2-buffer ring pipelined
// across chunk AND tile boundaries.
// ---------------------------------------------------------------------------
#define SMB_BIAS  0
#define SMB_B     512                             // bytes
#define SMB_A     (512 + 64 * PADB2 * 4)          // Bs: 64 x PADB2 half2
#define GEMM_SMEM (SMB_A + 2 * TILE_M * PADAH * 2)   // + 2 A buffers (half)

__device__ __forceinline__ void prefetch_chunk(const __half* __restrict__ A, int M,
                                               int row0, int c, __half* __restrict__ dst,
                                               int tid) {
    // 64 rows x 32 halfs = 4KB = 256 x 16B : one cp.async per thread
    int r = tid >> 2;                            // 0..63
    int seg = (tid & 3) << 3;                    // 0,8,16,24 halfs
    uint32_t d = smem_u32(dst + r * PADAH + c * 32 + seg);
    const __half* src = A + (size_t)(row0 + r) * DDIM + c * 32 + seg;
    cp_async16(d, src, row0 + r < M);
    cp_commit();
}

// One 32-k chunk = 2 fp16 k-steps of 16. As_c points at chunk base.
__device__ __forceinline__ void compute_chunk(
    const __half* __restrict__ As_c, const uint32_t* __restrict__ Bs, int kbase,
    int mrow, int ncol, int g, int t, float acc[8][4]) {
#pragma unroll
    for (int ks = 0; ks < 2; ks++) {
        int kk = ks * 16;
        uint32_t a[4];
        {
            const __half* r0 = As_c + (mrow + g) * PADAH + kk + 2 * t;
            const __half* r1 = r0 + 8 * PADAH;
            a[0] = *(const uint32_t*)(r0);
            a[1] = *(const uint32_t*)(r1);
            a[2] = *(const uint32_t*)(r0 + 8);
            a[3] = *(const uint32_t*)(r1 + 8);
        }
        int k2 = (kbase + kk) >> 1;
        uint32_t b[8][2];
#pragma unroll
        for (int nt = 0; nt < 8; nt++) {
            int cc = ncol + nt * 8 + g;
            b[nt][0] = Bs[(k2 + t) * PADB2 + cc];
            b[nt][1] = Bs[(k2 + t + 4) * PADB2 + cc];
        }
#pragma unroll
        for (int nt = 0; nt < 8; nt++)
            mma_m16n8k16_f16(acc[nt], a, b[nt]);
    }
}

template <typename OutT>
__global__ void __launch_bounds__(256, 3)
gemm_f16_pipe(const __half* __restrict__ A, const float* __restrict__ W,
              const float* __restrict__ bias, OutT* __restrict__ C,
              int M, int ntiles) {
    extern __shared__ char smraw[];
    float* bias_s = (float*)(smraw + SMB_BIAS);
    uint32_t* Bs = (uint32_t*)(smraw + SMB_B);
    __half* As = (__half*)(smraw + SMB_A);       // [2][TILE_M][PADAH]

    int tid = threadIdx.x;
    int wid = tid >> 5, lane = tid & 31;
    int g = lane >> 2, t = lane & 3;
    int mrow = (wid >> 1) * 16, ncol = (wid & 1) * 64;

    if (tid < 128) bias_s[tid] = bias[tid];
    // Stage W once as k-paired half2: Bs[k2][n] = {W[2k2][n], W[2k2+1][n]}
    for (int i = tid; i < 2048; i += 256) {
        int k2 = i >> 5;
        int n4 = (i & 31) << 2;
        float4 v0 = *(const float4*)(W + (size_t)(2 * k2) * DDIM + n4);
        float4 v1 = *(const float4*)(W + (size_t)(2 * k2 + 1) * DDIM + n4);
        uint32_t* p = &Bs[k2 * PADB2 + n4];
        p[0] = pack_h2(v0.x, v1.x);
        p[1] = pack_h2(v0.y, v1.y);
        p[2] = pack_h2(v0.z, v1.z);
        p[3] = pack_h2(v0.w, v1.w);
    }
    __syncthreads();

    int buf = 0;
    if (blockIdx.x < ntiles)
        prefetch_chunk(A, M, blockIdx.x * TILE_M, 0, As, tid);

    for (int tt = blockIdx.x; tt < ntiles; tt += gridDim.x) {
        int row0 = tt * TILE_M;
        float acc[8][4];
#pragma unroll
        for (int nt = 0; nt < 8; nt++)
#pragma unroll
            for (int j = 0; j < 4; j++) acc[nt][j] = 0.f;

#pragma unroll
        for (int c = 0; c < 4; c++) {
            asm volatile("cp.async.wait_group 0;" ::: "memory");
            __syncthreads();
            int nc = (c + 1) & 3;
            int ntile = (c == 3) ? tt + (int)gridDim.x : tt;
            if (ntile < ntiles)
                prefetch_chunk(A, M, ntile * TILE_M, nc,
                               As + (buf ^ 1) * TILE_M * PADAH, tid);
            compute_chunk(As + buf * TILE_M * PADAH + c * 32, Bs, c * 32,
                          mrow, ncol, g, t, acc);
            buf ^= 1;
        }

        // Epilogue: bias + relu
#pragma unroll
        for (int nt = 0; nt < 8; nt++) {
            int col = ncol + nt * 8 + t * 2;
            float2 bb = *(const float2*)(bias_s + col);
            int r0 = row0 + mrow + g;
            int r1 = r0 + 8;
            if (r0 < M)
                store2(C, (size_t)r0 * DDIM + col,
                       fmaxf(acc[nt][0] + bb.x, 0.f),
                       fmaxf(acc[nt][1] + bb.y, 0.f));
            if (r1 < M)
                store2(C, (size_t)r1 * DDIM + col,
                       fmaxf(acc[nt][2] + bb.x, 0.f),
                       fmaxf(acc[nt][3] + bb.y, 0.f));
        }
    }
}

// ---------------------------------------------------------------------------
extern "C" void kernel_launch(void* const* d_in, const int* in_sizes, int n_in,
                              void* d_out, int out_size) {
    const float* x  = (const float*)d_in[0];
    const void*  ei = d_in[1];
    const float* W1 = (const float*)d_in[2];
    const float* b1 = (const float*)d_in[3];
    const float* W2 = (const float*)d_in[4];
    const float* b2 = (const float*)d_in[5];

    int N = in_sizes[0] / DDIM;
    int E = in_sizes[1] / 2;
    int L = in_sizes[3] / DDIM;

    float* out = (float*)d_out;

    float *fb0, *fb1, *fb2, *fb3;
    int *cnt, *rowptr, *cursor, *esrc;
    cudaGetSymbolAddress((void**)&fb0,    g_b0);
    cudaGetSymbolAddress((void**)&fb1,    g_b1);
    cudaGetSymbolAddress((void**)&fb2,    g_b2);
    cudaGetSymbolAddress((void**)&fb3,    g_b3);
    cudaGetSymbolAddress((void**)&cnt,    g_cnt);
    cudaGetSymbolAddress((void**)&rowptr, g_rowptr);
    cudaGetSymbolAddress((void**)&cursor, g_cursor);
    cudaGetSymbolAddress((void**)&esrc,   g_esrc);

    __half* xh0  = (__half*)fb0;
    __half* xh1  = (__half*)fb1;
    __half* aggh = (__half*)fb2;
    __half* hh   = (__half*)fb3;

    static int smem_set = 0;
    if (!smem_set) {
        cudaFuncSetAttribute(gemm_f16_pipe<__half>,
                             cudaFuncAttributeMaxDynamicSharedMemorySize, GEMM_SMEM);
        cudaFuncSetAttribute(gemm_f16_pipe<float>,
                             cudaFuncAttributeMaxDynamicSharedMemorySize, GEMM_SMEM);
        smem_set = 1;
    }

    // ---- CSR build (once per launch) ----
    zero_cnt_kernel<<<(N + 255) / 256, 256>>>(cnt, N);
    hist_kernel<<<(E + 255) / 256, 256>>>(cnt, ei, E, N);
    scan_kernel<<<1, 1024>>>(cnt, rowptr, cursor, N);
    bucket_kernel<<<(E + 255) / 256, 256>>>(cursor, esrc, ei, E, N);

    int gather_blocks = (N + 7) / 8;
    int ntiles = (N + TILE_M - 1) / TILE_M;
    int gemm_grid = 3 * 148;
    if (gemm_grid > ntiles) gemm_grid = ntiles;

    const __half* cur = nullptr;
    for (int l = 0; l < L; l++) {
        if (l == 0)
            gather_agg_f16<float><<<gather_blocks, 256>>>(aggh, x, rowptr, esrc, N);
        else
            gather_agg_f16<__half><<<gather_blocks, 256>>>(aggh, cur, rowptr, esrc, N);

        gemm_f16_pipe<__half><<<gemm_grid, 256, GEMM_SMEM>>>(
            aggh, W1 + (size_t)l * DDIM * DDIM, b1 + (size_t)l * DDIM, hh, N, ntiles);

        if (l == L - 1) {
            gemm_f16_pipe<float><<<gemm_grid, 256, GEMM_SMEM>>>(
                hh, W2 + (size_t)l * DDIM * DDIM, b2 + (size_t)l * DDIM, out, N, ntiles);
        } else {
            __half* dst = (l & 1) ? xh1 : xh0;
            gemm_f16_pipe<__half><<<gemm_grid, 256, GEMM_SMEM>>>(
                hh, W2 + (size_t)l * DDIM * DDIM, b2 + (size_t)l * DDIM, dst, N, ntiles);
            cur = dst;
        }
    }
}

// round 16
// speedup vs baseline: 1.0303x; 1.0303x over previous
#include <cuda_runtime.h>
#include <cuda_fp16.h>
#include <cstdint>

#define DDIM 128
#define MAXN 50048
#define MAXE 2097152
#define PADB2 132   // Bs row stride (half2 words), rows indexed by k/2
#define PADAH 136   // As row stride (halfs) -> conflict-free fragment LDS

// Scratch (allocation-free: __device__ globals). Half buffers alias floats.
__device__ float g_b0[(size_t)MAXN * DDIM / 2];   // xh ping
__device__ float g_b1[(size_t)MAXN * DDIM / 2];   // xh pong
__device__ float g_b2[(size_t)MAXN * DDIM / 2];   // aggh
__device__ float g_b3[(size_t)MAXN * DDIM / 2];   // hh
__device__ int   g_cnt[MAXN];
__device__ int   g_rowptr[MAXN + 1];
__device__ int   g_cursor[MAXN];
__device__ int   g_esrc[MAXE];

// ---------------------------------------------------------------------------
// Helpers
// ---------------------------------------------------------------------------
__device__ __forceinline__ uint32_t smem_u32(const void* p) {
    uint32_t a;
    asm("{ .reg .u64 t; cvta.to.shared.u64 t, %1; cvt.u32.u64 %0, t; }"
        : "=r"(a) : "l"(p));
    return a;
}
__device__ __forceinline__ void cp_async16(uint32_t dst, const void* src, bool pred) {
    int sz = pred ? 16 : 0;
    asm volatile("cp.async.ca.shared.global [%0], [%1], 16, %2;"
                 :: "r"(dst), "l"(src), "r"(sz));
}
__device__ __forceinline__ void cp_commit() {
    asm volatile("cp.async.commit_group;" ::: "memory");
}
__device__ __forceinline__ uint32_t pack_h2(float lo, float hi) {
    __half2 h = __floats2half2_rn(lo, hi);
    return *(uint32_t*)&h;
}
__device__ __forceinline__ void mma_m16n8k16_f16(float c[4], const uint32_t a[4],
                                                 const uint32_t b[2]) {
    asm volatile(
        "mma.sync.aligned.m16n8k16.row.col.f32.f16.f16.f32 "
        "{%0,%1,%2,%3}, {%4,%5,%6,%7}, {%8,%9}, {%0,%1,%2,%3};\n"
        : "+f"(c[0]), "+f"(c[1]), "+f"(c[2]), "+f"(c[3])
        : "r"(a[0]), "r"(a[1]), "r"(a[2]), "r"(a[3]), "r"(b[0]), "r"(b[1]));
}
__device__ __forceinline__ void store2(float* C, size_t idx, float x, float y) {
    float2 o; o.x = x; o.y = y;
    *(float2*)(C + idx) = o;
}
__device__ __forceinline__ void store2(__half* C, size_t idx, float x, float y) {
    *(uint32_t*)(C + idx) = pack_h2(x, y);
}

// ---------------------------------------------------------------------------
// Edge dtype self-detection (int64 vs int32). When int64, indices fit in the
// low 32-bit word (N < 2^31) -> narrow loads halve edge traffic.
// ---------------------------------------------------------------------------
__device__ __forceinline__ bool edges_are_i64(const void* ei, int N) {
    const long long* e64 = (const long long*)ei;
#pragma unroll
    for (int i = 0; i < 4; i++) {
        long long v = e64[i];
        if (v < 0 || v >= (long long)N) return false;
    }
    return true;
}

__global__ void zero_cnt_kernel(int* cnt, int n) {
    int i = blockIdx.x * blockDim.x + threadIdx.x;
    if (i < n) cnt[i] = 0;
}

__global__ void hist_kernel(int* cnt, const void* ei, int E, int N) {
    int i = blockIdx.x * blockDim.x + threadIdx.x;
    if (i >= E) return;
    bool is64 = edges_are_i64(ei, N);
    const int* e32 = (const int*)ei;
    int d = is64 ? e32[2 * ((size_t)E + i)] : e32[E + i];
    atomicAdd(&cnt[d], 1);
}

__global__ void scan_kernel(const int* __restrict__ cnt, int* __restrict__ rowptr,
                            int* __restrict__ cursor, int N) {
    __shared__ int part[1024];
    int tid = threadIdx.x;
    int chunk = (N + 1023) / 1024;
    int start = tid * chunk;
    int end = min(start + chunk, N);
    int s = 0;
    for (int i = start; i < end; i++) s += cnt[i];
    part[tid] = s;
    __syncthreads();
    for (int off = 1; off < 1024; off <<= 1) {
        int v = (tid >= off) ? part[tid - off] : 0;
        __syncthreads();
        part[tid] += v;
        __syncthreads();
    }
    int run = (tid == 0) ? 0 : part[tid - 1];
    for (int i = start; i < end; i++) {
        rowptr[i] = run;
        cursor[i] = run;
        run += cnt[i];
    }
    if (end == N) rowptr[N] = run;
}

__global__ void bucket_kernel(int* __restrict__ cursor, int* __restrict__ esrc,
                              const void* ei, int E, int N) {
    int i = blockIdx.x * blockDim.x + threadIdx.x;
    if (i >= E) return;
    bool is64 = edges_are_i64(ei, N);
    const int* e32 = (const int*)ei;
    int s, d;
    if (is64) {
        s = e32[2 * (size_t)i];
        d = e32[2 * ((size_t)E + i)];
    } else {
        s = e32[i];
        d = e32[E + i];
    }
    int pos = atomicAdd(&cursor[d], 1);
    esrc[pos] = s;
}

// ---------------------------------------------------------------------------
// Layer-0 gather (fp32 input): one warp per node, lane = 4 cols, MLP-8.
// ---------------------------------------------------------------------------
__global__ void gather_agg_f32in(__half* __restrict__ agg, const float* __restrict__ x,
                                 const int* __restrict__ rowptr,
                                 const int* __restrict__ esrc, int N) {
    int node = blockIdx.x * (blockDim.x >> 5) + (threadIdx.x >> 5);
    if (node >= N) return;
    int lane = threadIdx.x & 31;

    float4 u = ((const float4*)(x + (size_t)node * DDIM))[lane];
    float acc0 = u.x, acc1 = u.y, acc2 = u.z, acc3 = u.w;
    int b = rowptr[node];
    int e = rowptr[node + 1];

    for (int base = b; base < e; base += 32) {
        int m = min(32, e - base);
        int sv = (lane < m) ? esrc[base + lane] : 0;
        for (int j0 = 0; j0 < m; j0 += 8) {
            float4 v[8];
#pragma unroll
            for (int jj = 0; jj < 8; jj++) {
                int s = __shfl_sync(0xffffffffu, sv, (j0 + jj) & 31);
                v[jj] = (j0 + jj < m) ? ((const float4*)(x + (size_t)s * DDIM))[lane]
                                      : make_float4(0.f, 0.f, 0.f, 0.f);
            }
#pragma unroll
            for (int jj = 0; jj < 8; jj++) {
                acc0 += v[jj].x; acc1 += v[jj].y; acc2 += v[jj].z; acc3 += v[jj].w;
            }
        }
    }
    uint2 o;
    o.x = pack_h2(acc0, acc1);
    o.y = pack_h2(acc2, acc3);
    ((uint2*)(agg + (size_t)node * DDIM))[lane] = o;
}

// ---------------------------------------------------------------------------
// fp16 gather: one warp per node, HALF-WARP per neighbor row.
// Lane loads uint4 (8 halfs); 16 lanes cover a 128-half row; the two
// half-warps process different neighbors in parallel (2x MLP, half the LDGs).
// Final cross-half shfl_xor(16) reduction; lanes 0-15 write the row.
// ---------------------------------------------------------------------------
__global__ void gather_agg_h16(__half* __restrict__ agg, const __half* __restrict__ x,
                               const int* __restrict__ rowptr,
                               const int* __restrict__ esrc, int N) {
    int node = blockIdx.x * (blockDim.x >> 5) + (threadIdx.x >> 5);
    if (node >= N) return;
    int lane = threadIdx.x & 31;
    int hid = lane >> 4;          // half-warp id
    int l16 = lane & 15;          // 8-half column segment

    float acc[8];
    {
        uint4 u = make_uint4(0u, 0u, 0u, 0u);
        if (hid == 0)
            u = ((const uint4*)(x + (size_t)node * DDIM))[l16];
        uint32_t w[4] = {u.x, u.y, u.z, u.w};
#pragma unroll
        for (int q = 0; q < 4; q++) {
            float2 p = __half22float2(*(__half2*)&w[q]);
            acc[2 * q] = p.x; acc[2 * q + 1] = p.y;
        }
    }

    int b = rowptr[node];
    int e = rowptr[node + 1];
    for (int base = b; base < e; base += 32) {
        int m = min(32, e - base);
        int sv = (lane < m) ? esrc[base + lane] : 0;
        for (int j0 = 0; j0 < m; j0 += 16) {
            uint4 v[8];
#pragma unroll
            for (int jj = 0; jj < 8; jj++) {
                int j = j0 + 2 * jj + hid;
                int s = __shfl_sync(0xffffffffu, sv, j & 31);
                v[jj] = (j < m) ? ((const uint4*)(x + (size_t)s * DDIM))[l16]
                                : make_uint4(0u, 0u, 0u, 0u);
            }
#pragma unroll
            for (int jj = 0; jj < 8; jj++) {
                uint32_t w[4] = {v[jj].x, v[jj].y, v[jj].z, v[jj].w};
#pragma unroll
                for (int q = 0; q < 4; q++) {
                    float2 p = __half22float2(*(__half2*)&w[q]);
                    acc[2 * q] += p.x; acc[2 * q + 1] += p.y;
                }
            }
        }
    }

#pragma unroll
    for (int q = 0; q < 8; q++)
        acc[q] += __shfl_xor_sync(0xffffffffu, acc[q], 16);

    if (hid == 0) {
        uint4 o;
        o.x = pack_h2(acc[0], acc[1]);
        o.y = pack_h2(acc[2], acc[3]);
        o.z = pack_h2(acc[4], acc[5]);
        o.w = pack_h2(acc[6], acc[7]);
        ((uint4*)(agg + (size_t)node * DDIM))[l16] = o;
    }
}

// ---------------------------------------------------------------------------
// Persistent pipelined FP16 GEMM (m16n8k16, fp32 accum), fp16 A in gmem:
//   C[M,128] = relu(A[M,128] @ W[128,128] + bias)   (C fp16 or fp32)
// 128x128 tile. W staged once as k-paired half2. A via cp.async 2-buffer ring
// pipelined across chunk AND tile boundaries. 8 warps, 4(m)x2(n), 32x64 each.
// ---------------------------------------------------------------------------
#define SMB_BIAS  0
#define SMB_B     512                             // bytes
#define SMB_A     (512 + 64 * PADB2 * 4)          // Bs: 64 x PADB2 half2
#define GEMM_SMEM (SMB_A + 2 * 128 * PADAH * 2)   // + 2 A buffers (half)

__device__ __forceinline__ void prefetch_chunk(const __half* __restrict__ A, int M,
                                               int row0, int c, __half* __restrict__ dst,
                                               int tid) {
#pragma unroll
    for (int j = 0; j < 2; j++) {
        int i = tid + j * 256;                   // 0..511
        int r = i >> 2;                          // 0..127
        int seg = (i & 3) << 3;                  // 0,8,16,24 halfs
        uint32_t d = smem_u32(dst + r * PADAH + c * 32 + seg);
        const __half* src = A + (size_t)(row0 + r) * DDIM + c * 32 + seg;
        cp_async16(d, src, row0 + r < M);
    }
    cp_commit();
}

// One 32-k chunk = 2 fp16 k-steps of 16. As_c points at chunk base.
__device__ __forceinline__ void compute_chunk(
    const __half* __restrict__ As_c, const uint32_t* __restrict__ Bs, int kbase,
    int mrow, int ncol, int g, int t, float acc[2][8][4]) {
#pragma unroll
    for (int ks = 0; ks < 2; ks++) {
        int kk = ks * 16;
        uint32_t a[2][4];
#pragma unroll
        for (int mt = 0; mt < 2; mt++) {
            const __half* r0 = As_c + (mrow + mt * 16 + g) * PADAH + kk + 2 * t;
            const __half* r1 = r0 + 8 * PADAH;
            a[mt][0] = *(const uint32_t*)(r0);
            a[mt][1] = *(const uint32_t*)(r1);
            a[mt][2] = *(const uint32_t*)(r0 + 8);
            a[mt][3] = *(const uint32_t*)(r1 + 8);
        }
        int k2 = (kbase + kk) >> 1;
        uint32_t b[8][2];
#pragma unroll
        for (int nt = 0; nt < 8; nt++) {
            int cc = ncol + nt * 8 + g;
            b[nt][0] = Bs[(k2 + t) * PADB2 + cc];
            b[nt][1] = Bs[(k2 + t + 4) * PADB2 + cc];
        }
#pragma unroll
        for (int mt = 0; mt < 2; mt++)
#pragma unroll
            for (int nt = 0; nt < 8; nt++)
                mma_m16n8k16_f16(acc[mt][nt], a[mt], b[nt]);
    }
}

template <typename OutT>
__global__ void __launch_bounds__(256, 2)
gemm_f16_pipe(const __half* __restrict__ A, const float* __restrict__ W,
              const float* __restrict__ bias, OutT* __restrict__ C,
              int M, int ntiles) {
    extern __shared__ char smraw[];
    float* bias_s = (float*)(smraw + SMB_BIAS);
    uint32_t* Bs = (uint32_t*)(smraw + SMB_B);
    __half* As = (__half*)(smraw + SMB_A);       // [2][128][PADAH]

    int tid = threadIdx.x;
    int wid = tid >> 5, lane = tid & 31;
    int g = lane >> 2, t = lane & 3;
    int mrow = (wid >> 1) * 32, ncol = (wid & 1) * 64;

    if (tid < 128) bias_s[tid] = bias[tid];
    // Stage W once as k-paired half2: Bs[k2][n] = {W[2k2][n], W[2k2+1][n]}
    for (int i = tid; i < 2048; i += 256) {
        int k2 = i >> 5;
        int n4 = (i & 31) << 2;
        float4 v0 = *(const float4*)(W + (size_t)(2 * k2) * DDIM + n4);
        float4 v1 = *(const float4*)(W + (size_t)(2 * k2 + 1) * DDIM + n4);
        uint32_t* p = &Bs[k2 * PADB2 + n4];
        p[0] = pack_h2(v0.x, v1.x);
        p[1] = pack_h2(v0.y, v1.y);
        p[2] = pack_h2(v0.z, v1.z);
        p[3] = pack_h2(v0.w, v1.w);
    }
    __syncthreads();

    int buf = 0;
    if (blockIdx.x < ntiles)
        prefetch_chunk(A, M, blockIdx.x << 7, 0, As, tid);

    for (int tt = blockIdx.x; tt < ntiles; tt += gridDim.x) {
        int row0 = tt << 7;
        float acc[2][8][4];
#pragma unroll
        for (int mt = 0; mt < 2; mt++)
#pragma unroll
            for (int nt = 0; nt < 8; nt++)
#pragma unroll
                for (int j = 0; j < 4; j++) acc[mt][nt][j] = 0.f;

#pragma unroll
        for (int c = 0; c < 4; c++) {
            asm volatile("cp.async.wait_group 0;" ::: "memory");
            __syncthreads();
            int nc = (c + 1) & 3;
            int ntile = (c == 3) ? tt + (int)gridDim.x : tt;
            if (ntile < ntiles)
                prefetch_chunk(A, M, ntile << 7, nc, As + (buf ^ 1) * 128 * PADAH, tid);
            compute_chunk(As + buf * 128 * PADAH + c * 32, Bs, c * 32,
                          mrow, ncol, g, t, acc);
            buf ^= 1;
        }

        // Epilogue: bias + relu
#pragma unroll
        for (int nt = 0; nt < 8; nt++) {
            int col = ncol + nt * 8 + t * 2;
            float2 bb = *(const float2*)(bias_s + col);
#pragma unroll
            for (int mt = 0; mt < 2; mt++) {
                int r0 = row0 + mrow + mt * 16 + g;
                int r1 = r0 + 8;
                if (r0 < M)
                    store2(C, (size_t)r0 * DDIM + col,
                           fmaxf(acc[mt][nt][0] + bb.x, 0.f),
                           fmaxf(acc[mt][nt][1] + bb.y, 0.f));
                if (r1 < M)
                    store2(C, (size_t)r1 * DDIM + col,
                           fmaxf(acc[mt][nt][2] + bb.x, 0.f),
                           fmaxf(acc[mt][nt][3] + bb.y, 0.f));
            }
        }
    }
}

// ---------------------------------------------------------------------------
extern "C" void kernel_launch(void* const* d_in, const int* in_sizes, int n_in,
                              void* d_out, int out_size) {
    const float* x  = (const float*)d_in[0];
    const void*  ei = d_in[1];
    const float* W1 = (const float*)d_in[2];
    const float* b1 = (const float*)d_in[3];
    const float* W2 = (const float*)d_in[4];
    const float* b2 = (const float*)d_in[5];

    int N = in_sizes[0] / DDIM;
    int E = in_sizes[1] / 2;
    int L = in_sizes[3] / DDIM;

    float* out = (float*)d_out;

    float *fb0, *fb1, *fb2, *fb3;
    int *cnt, *rowptr, *cursor, *esrc;
    cudaGetSymbolAddress((void**)&fb0,    g_b0);
    cudaGetSymbolAddress((void**)&fb1,    g_b1);
    cudaGetSymbolAddress((void**)&fb2,    g_b2);
    cudaGetSymbolAddress((void**)&fb3,    g_b3);
    cudaGetSymbolAddress((void**)&cnt,    g_cnt);
    cudaGetSymbolAddress((void**)&rowptr, g_rowptr);
    cudaGetSymbolAddress((void**)&cursor, g_cursor);
    cudaGetSymbolAddress((void**)&esrc,   g_esrc);

    __half* xh0  = (__half*)fb0;
    __half* xh1  = (__half*)fb1;
    __half* aggh = (__half*)fb2;
    __half* hh   = (__half*)fb3;

    static int smem_set = 0;
    if (!smem_set) {
        cudaFuncSetAttribute(gemm_f16_pipe<__half>,
                             cudaFuncAttributeMaxDynamicSharedMemorySize, GEMM_SMEM);
        cudaFuncSetAttribute(gemm_f16_pipe<float>,
                             cudaFuncAttributeMaxDynamicSharedMemorySize, GEMM_SMEM);
        smem_set = 1;
    }

    // ---- CSR build (once per launch) ----
    zero_cnt_kernel<<<(N + 255) / 256, 256>>>(cnt, N);
    hist_kernel<<<(E + 255) / 256, 256>>>(cnt, ei, E, N);
    scan_kernel<<<1, 1024>>>(cnt, rowptr, cursor, N);
    bucket_kernel<<<(E + 255) / 256, 256>>>(cursor, esrc, ei, E, N);

    int gather_blocks = (N + 7) / 8;
    int ntiles = (N + 127) / 128;
    int gemm_grid = 2 * 148;
    if (gemm_grid > ntiles) gemm_grid = ntiles;

    const __half* cur = nullptr;
    for (int l = 0; l < L; l++) {
        if (l == 0)
            gather_agg_f32in<<<gather_blocks, 256>>>(aggh, x, rowptr, esrc, N);
        else
            gather_agg_h16<<<gather_blocks, 256>>>(aggh, cur, rowptr, esrc, N);

        gemm_f16_pipe<__half><<<gemm_grid, 256, GEMM_SMEM>>>(
            aggh, W1 + (size_t)l * DDIM * DDIM, b1 + (size_t)l * DDIM, hh, N, ntiles);

        if (l == L - 1) {
            gemm_f16_pipe<float><<<gemm_grid, 256, GEMM_SMEM>>>(
                hh, W2 + (size_t)l * DDIM * DDIM, b2 + (size_t)l * DDIM, out, N, ntiles);
        } else {
            __half* dst = (l & 1) ? xh1 : xh0;
            gemm_f16_pipe<__half><<<gemm_grid, 256, GEMM_SMEM>>>(
                hh, W2 + (size_t)l * DDIM * DDIM, b2 + (size_t)l * DDIM, dst, N, ntiles);
            cur = dst;
        }
    }
}

// round 17
// speedup vs baseline: 1.0661x; 1.0348x over previous
#include <cuda_runtime.h>
#include <cuda_fp16.h>
#include <cstdint>

#define DDIM 128
#define MAXN 50048
#define MAXE 2097152
#define PADB2 132   // Bs row stride (half2 words), rows indexed by k/2
#define PADAH 136   // As row stride (halfs) -> conflict-free fragment LDS

// Scratch (allocation-free: __device__ globals). Half buffers alias floats.
__device__ float g_b0[(size_t)MAXN * DDIM / 2];   // xh ping
__device__ float g_b1[(size_t)MAXN * DDIM / 2];   // xh pong
__device__ float g_b2[(size_t)MAXN * DDIM / 2];   // aggh
__device__ float g_b3[(size_t)MAXN * DDIM / 2];   // hh
__device__ int   g_cnt[MAXN];
__device__ int   g_rowptr[MAXN + 1];
__device__ int   g_cursor[MAXN];
__device__ int   g_esrc[MAXE];

// ---------------------------------------------------------------------------
// Helpers
// ---------------------------------------------------------------------------
__device__ __forceinline__ uint32_t smem_u32(const void* p) {
    uint32_t a;
    asm("{ .reg .u64 t; cvta.to.shared.u64 t, %1; cvt.u32.u64 %0, t; }"
        : "=r"(a) : "l"(p));
    return a;
}
__device__ __forceinline__ void cp_async16(uint32_t dst, const void* src, bool pred) {
    int sz = pred ? 16 : 0;
    asm volatile("cp.async.ca.shared.global [%0], [%1], 16, %2;"
                 :: "r"(dst), "l"(src), "r"(sz));
}
__device__ __forceinline__ void cp_commit() {
    asm volatile("cp.async.commit_group;" ::: "memory");
}
__device__ __forceinline__ uint32_t pack_h2(float lo, float hi) {
    __half2 h = __floats2half2_rn(lo, hi);
    return *(uint32_t*)&h;
}
__device__ __forceinline__ void mma_m16n8k16_f16(float c[4], const uint32_t a[4],
                                                 const uint32_t b[2]) {
    asm volatile(
        "mma.sync.aligned.m16n8k16.row.col.f32.f16.f16.f32 "
        "{%0,%1,%2,%3}, {%4,%5,%6,%7}, {%8,%9}, {%0,%1,%2,%3};\n"
        : "+f"(c[0]), "+f"(c[1]), "+f"(c[2]), "+f"(c[3])
        : "r"(a[0]), "r"(a[1]), "r"(a[2]), "r"(a[3]), "r"(b[0]), "r"(b[1]));
}
__device__ __forceinline__ void store2(float* C, size_t idx, float x, float y) {
    float2 o; o.x = x; o.y = y;
    *(float2*)(C + idx) = o;
}
__device__ __forceinline__ void store2(__half* C, size_t idx, float x, float y) {
    *(uint32_t*)(C + idx) = pack_h2(x, y);
}

// Per-dtype row payload for the gather (4 values per lane).
template <typename T> struct RowVec;
template <> struct RowVec<__half> {
    using V = uint2;
    static __device__ __forceinline__ V zero() { return make_uint2(0u, 0u); }
    static __device__ __forceinline__ void add(float& a0, float& a1, float& a2,
                                               float& a3, V v) {
        float2 p0 = __half22float2(*(__half2*)&v.x);
        float2 p1 = __half22float2(*(__half2*)&v.y);
        a0 += p0.x; a1 += p0.y; a2 += p1.x; a3 += p1.y;
    }
};
template <> struct RowVec<float> {
    using V = float4;
    static __device__ __forceinline__ V zero() { return make_float4(0.f, 0.f, 0.f, 0.f); }
    static __device__ __forceinline__ void add(float& a0, float& a1, float& a2,
                                               float& a3, V v) {
        a0 += v.x; a1 += v.y; a2 += v.z; a3 += v.w;
    }
};

// ---------------------------------------------------------------------------
// Edge dtype self-detection (int64 vs int32). When int64, indices fit in the
// low 32-bit word (N < 2^31) -> narrow loads halve edge traffic.
// ---------------------------------------------------------------------------
__device__ __forceinline__ bool edges_are_i64(const void* ei, int N) {
    const long long* e64 = (const long long*)ei;
#pragma unroll
    for (int i = 0; i < 4; i++) {
        long long v = e64[i];
        if (v < 0 || v >= (long long)N) return false;
    }
    return true;
}

__global__ void zero_cnt_kernel(int* cnt, int n) {
    int i = blockIdx.x * blockDim.x + threadIdx.x;
    if (i < n) cnt[i] = 0;
}

// 2 edges per thread: batch loads before atomics (MLP-2 on the latency chain).
__global__ void hist_kernel(int* cnt, const void* ei, int E, int N) {
    int i0 = (blockIdx.x * blockDim.x + threadIdx.x) * 2;
    if (i0 >= E) return;
    bool is64 = edges_are_i64(ei, N);
    const int* e32 = (const int*)ei;
    int d0 = is64 ? e32[2 * ((size_t)E + i0)] : e32[E + i0];
    bool has1 = (i0 + 1 < E);
    int d1 = 0;
    if (has1) d1 = is64 ? e32[2 * ((size_t)E + i0 + 1)] : e32[E + i0 + 1];
    atomicAdd(&cnt[d0], 1);
    if (has1) atomicAdd(&cnt[d1], 1);
}

__global__ void scan_kernel(const int* __restrict__ cnt, int* __restrict__ rowptr,
                            int* __restrict__ cursor, int N) {
    __shared__ int part[1024];
    int tid = threadIdx.x;
    int chunk = (N + 1023) / 1024;
    int start = tid * chunk;
    int end = min(start + chunk, N);
    int s = 0;
    for (int i = start; i < end; i++) s += cnt[i];
    part[tid] = s;
    __syncthreads();
    for (int off = 1; off < 1024; off <<= 1) {
        int v = (tid >= off) ? part[tid - off] : 0;
        __syncthreads();
        part[tid] += v;
        __syncthreads();
    }
    int run = (tid == 0) ? 0 : part[tid - 1];
    for (int i = start; i < end; i++) {
        rowptr[i] = run;
        cursor[i] = run;
        run += cnt[i];
    }
    if (end == N) rowptr[N] = run;
}

// 2 edges per thread: batch all loads, then atomics, then stores.
__global__ void bucket_kernel(int* __restrict__ cursor, int* __restrict__ esrc,
                              const void* ei, int E, int N) {
    int i0 = (blockIdx.x * blockDim.x + threadIdx.x) * 2;
    if (i0 >= E) return;
    bool is64 = edges_are_i64(ei, N);
    const int* e32 = (const int*)ei;
    bool has1 = (i0 + 1 < E);
    int s0, d0, s1 = 0, d1 = 0;
    if (is64) {
        s0 = e32[2 * (size_t)i0];
        d0 = e32[2 * ((size_t)E + i0)];
        if (has1) {
            s1 = e32[2 * ((size_t)i0 + 1)];
            d1 = e32[2 * ((size_t)E + i0 + 1)];
        }
    } else {
        s0 = e32[i0];
        d0 = e32[E + i0];
        if (has1) {
            s1 = e32[i0 + 1];
            d1 = e32[E + i0 + 1];
        }
    }
    int pos0 = atomicAdd(&cursor[d0], 1);
    int pos1 = has1 ? atomicAdd(&cursor[d1], 1) : 0;
    esrc[pos0] = s0;
    if (has1) esrc[pos1] = s1;
}

// ---------------------------------------------------------------------------
// aggh[i] = fp16( x[i] + sum_{s in in-nb(i)} x[s] )  (fp32 accum).
// One warp per node; MLP-8 batched neighbor row prefetch. T = __half or float.
// ---------------------------------------------------------------------------
template <typename T>
__global__ void gather_agg_f16(__half* __restrict__ agg, const T* __restrict__ x,
                               const int* __restrict__ rowptr,
                               const int* __restrict__ esrc, int N) {
    using RV = RowVec<T>;
    using V = typename RV::V;
    int node = blockIdx.x * (blockDim.x >> 5) + (threadIdx.x >> 5);
    if (node >= N) return;
    int lane = threadIdx.x & 31;

    float acc0 = 0.f, acc1 = 0.f, acc2 = 0.f, acc3 = 0.f;
    {
        V u = ((const V*)(x + (size_t)node * DDIM))[lane];
        RV::add(acc0, acc1, acc2, acc3, u);
    }
    int b = rowptr[node];
    int e = rowptr[node + 1];

    for (int base = b; base < e; base += 32) {
        int m = min(32, e - base);
        int sv = (lane < m) ? esrc[base + lane] : 0;
        for (int j0 = 0; j0 < m; j0 += 8) {
            V v[8];
#pragma unroll
            for (int jj = 0; jj < 8; jj++) {
                int s = __shfl_sync(0xffffffffu, sv, (j0 + jj) & 31);
                v[jj] = (j0 + jj < m) ? ((const V*)(x + (size_t)s * DDIM))[lane]
                                      : RV::zero();
            }
#pragma unroll
            for (int jj = 0; jj < 8; jj++)
                RV::add(acc0, acc1, acc2, acc3, v[jj]);
        }
    }
    uint2 o;
    o.x = pack_h2(acc0, acc1);
    o.y = pack_h2(acc2, acc3);
    ((uint2*)(agg + (size_t)node * DDIM))[lane] = o;
}

// ---------------------------------------------------------------------------
// Persistent pipelined FP16 GEMM (m16n8k16, fp32 accum), fp16 A in gmem:
//   C[M,128] = relu(A[M,128] @ W[128,128] + bias)   (C fp16 or fp32)
// 128x128 tile. W staged once as k-paired half2. A via cp.async 2-buffer ring
// pipelined across chunk AND tile boundaries. 8 warps, 4(m)x2(n), 32x64 each.
// ---------------------------------------------------------------------------
#define SMB_BIAS  0
#define SMB_B     512                             // bytes
#define SMB_A     (512 + 64 * PADB2 * 4)          // Bs: 64 x PADB2 half2
#define GEMM_SMEM (SMB_A + 2 * 128 * PADAH * 2)   // + 2 A buffers (half)

__device__ __forceinline__ void prefetch_chunk(const __half* __restrict__ A, int M,
                                               int row0, int c, __half* __restrict__ dst,
                                               int tid) {
#pragma unroll
    for (int j = 0; j < 2; j++) {
        int i = tid + j * 256;                   // 0..511
        int r = i >> 2;                          // 0..127
        int seg = (i & 3) << 3;                  // 0,8,16,24 halfs
        uint32_t d = smem_u32(dst + r * PADAH + c * 32 + seg);
        const __half* src = A + (size_t)(row0 + r) * DDIM + c * 32 + seg;
        cp_async16(d, src, row0 + r < M);
    }
    cp_commit();
}

// One 32-k chunk = 2 fp16 k-steps of 16. As_c points at chunk base.
__device__ __forceinline__ void compute_chunk(
    const __half* __restrict__ As_c, const uint32_t* __restrict__ Bs, int kbase,
    int mrow, int ncol, int g, int t, float acc[2][8][4]) {
#pragma unroll
    for (int ks = 0; ks < 2; ks++) {
        int kk = ks * 16;
        uint32_t a[2][4];
#pragma unroll
        for (int mt = 0; mt < 2; mt++) {
            const __half* r0 = As_c + (mrow + mt * 16 + g) * PADAH + kk + 2 * t;
            const __half* r1 = r0 + 8 * PADAH;
            a[mt][0] = *(const uint32_t*)(r0);
            a[mt][1] = *(const uint32_t*)(r1);
            a[mt][2] = *(const uint32_t*)(r0 + 8);
            a[mt][3] = *(const uint32_t*)(r1 + 8);
        }
        int k2 = (kbase + kk) >> 1;
        uint32_t b[8][2];
#pragma unroll
        for (int nt = 0; nt < 8; nt++) {
            int cc = ncol + nt * 8 + g;
            b[nt][0] = Bs[(k2 + t) * PADB2 + cc];
            b[nt][1] = Bs[(k2 + t + 4) * PADB2 + cc];
        }
#pragma unroll
        for (int mt = 0; mt < 2; mt++)
#pragma unroll
            for (int nt = 0; nt < 8; nt++)
                mma_m16n8k16_f16(acc[mt][nt], a[mt], b[nt]);
    }
}

template <typename OutT>
__global__ void __launch_bounds__(256, 2)
gemm_f16_pipe(const __half* __restrict__ A, const float* __restrict__ W,
              const float* __restrict__ bias, OutT* __restrict__ C,
              int M, int ntiles) {
    extern __shared__ char smraw[];
    float* bias_s = (float*)(smraw + SMB_BIAS);
    uint32_t* Bs = (uint32_t*)(smraw + SMB_B);
    __half* As = (__half*)(smraw + SMB_A);       // [2][128][PADAH]

    int tid = threadIdx.x;
    int wid = tid >> 5, lane = tid & 31;
    int g = lane >> 2, t = lane & 3;
    int mrow = (wid >> 1) * 32, ncol = (wid & 1) * 64;

    if (tid < 128) bias_s[tid] = bias[tid];
    // Stage W once as k-paired half2: Bs[k2][n] = {W[2k2][n], W[2k2+1][n]}
    for (int i = tid; i < 2048; i += 256) {
        int k2 = i >> 5;
        int n4 = (i & 31) << 2;
        float4 v0 = *(const float4*)(W + (size_t)(2 * k2) * DDIM + n4);
        float4 v1 = *(const float4*)(W + (size_t)(2 * k2 + 1) * DDIM + n4);
        uint32_t* p = &Bs[k2 * PADB2 + n4];
        p[0] = pack_h2(v0.x, v1.x);
        p[1] = pack_h2(v0.y, v1.y);
        p[2] = pack_h2(v0.z, v1.z);
        p[3] = pack_h2(v0.w, v1.w);
    }
    __syncthreads();

    int buf = 0;
    if (blockIdx.x < ntiles)
        prefetch_chunk(A, M, blockIdx.x << 7, 0, As, tid);

    for (int tt = blockIdx.x; tt < ntiles; tt += gridDim.x) {
        int row0 = tt << 7;
        float acc[2][8][4];
#pragma unroll
        for (int mt = 0; mt < 2; mt++)
#pragma unroll
            for (int nt = 0; nt < 8; nt++)
#pragma unroll
                for (int j = 0; j < 4; j++) acc[mt][nt][j] = 0.f;

#pragma unroll
        for (int c = 0; c < 4; c++) {
            asm volatile("cp.async.wait_group 0;" ::: "memory");
            __syncthreads();
            int nc = (c + 1) & 3;
            int ntile = (c == 3) ? tt + (int)gridDim.x : tt;
            if (ntile < ntiles)
                prefetch_chunk(A, M, ntile << 7, nc, As + (buf ^ 1) * 128 * PADAH, tid);
            compute_chunk(As + buf * 128 * PADAH + c * 32, Bs, c * 32,
                          mrow, ncol, g, t, acc);
            buf ^= 1;
        }

        // Epilogue: bias + relu
#pragma unroll
        for (int nt = 0; nt < 8; nt++) {
            int col = ncol + nt * 8 + t * 2;
            float2 bb = *(const float2*)(bias_s + col);
#pragma unroll
            for (int mt = 0; mt < 2; mt++) {
                int r0 = row0 + mrow + mt * 16 + g;
                int r1 = r0 + 8;
                if (r0 < M)
                    store2(C, (size_t)r0 * DDIM + col,
                           fmaxf(acc[mt][nt][0] + bb.x, 0.f),
                           fmaxf(acc[mt][nt][1] + bb.y, 0.f));
                if (r1 < M)
                    store2(C, (size_t)r1 * DDIM + col,
                           fmaxf(acc[mt][nt][2] + bb.x, 0.f),
                           fmaxf(acc[mt][nt][3] + bb.y, 0.f));
            }
        }
    }
}

// ---------------------------------------------------------------------------
extern "C" void kernel_launch(void* const* d_in, const int* in_sizes, int n_in,
                              void* d_out, int out_size) {
    const float* x  = (const float*)d_in[0];
    const void*  ei = d_in[1];
    const float* W1 = (const float*)d_in[2];
    const float* b1 = (const float*)d_in[3];
    const float* W2 = (const float*)d_in[4];
    const float* b2 = (const float*)d_in[5];

    int N = in_sizes[0] / DDIM;
    int E = in_sizes[1] / 2;
    int L = in_sizes[3] / DDIM;

    float* out = (float*)d_out;

    float *fb0, *fb1, *fb2, *fb3;
    int *cnt, *rowptr, *cursor, *esrc;
    cudaGetSymbolAddress((void**)&fb0,    g_b0);
    cudaGetSymbolAddress((void**)&fb1,    g_b1);
    cudaGetSymbolAddress((void**)&fb2,    g_b2);
    cudaGetSymbolAddress((void**)&fb3,    g_b3);
    cudaGetSymbolAddress((void**)&cnt,    g_cnt);
    cudaGetSymbolAddress((void**)&rowptr, g_rowptr);
    cudaGetSymbolAddress((void**)&cursor, g_cursor);
    cudaGetSymbolAddress((void**)&esrc,   g_esrc);

    __half* xh0  = (__half*)fb0;
    __half* xh1  = (__half*)fb1;
    __half* aggh = (__half*)fb2;
    __half* hh   = (__half*)fb3;

    static int smem_set = 0;
    if (!smem_set) {
        cudaFuncSetAttribute(gemm_f16_pipe<__half>,
                             cudaFuncAttributeMaxDynamicSharedMemorySize, GEMM_SMEM);
        cudaFuncSetAttribute(gemm_f16_pipe<float>,
                             cudaFuncAttributeMaxDynamicSharedMemorySize, GEMM_SMEM);
        smem_set = 1;
    }

    // ---- CSR build (once per launch) ----
    zero_cnt_kernel<<<(N + 255) / 256, 256>>>(cnt, N);
    hist_kernel<<<(E / 2 + 256) / 256, 256>>>(cnt, ei, E, N);
    scan_kernel<<<1, 1024>>>(cnt, rowptr, cursor, N);
    bucket_kernel<<<(E / 2 + 256) / 256, 256>>>(cursor, esrc, ei, E, N);

    int gather_blocks = (N + 7) / 8;
    int ntiles = (N + 127) / 128;
    int gemm_grid = 2 * 148;
    if (gemm_grid > ntiles) gemm_grid = ntiles;

    const __half* cur = nullptr;
    for (int l = 0; l < L; l++) {
        // Layer 0 gathers straight from the fp32 input (no cvt pass needed).
        if (l == 0)
            gather_agg_f16<float><<<gather_blocks, 256>>>(aggh, x, rowptr, esrc, N);
        else
            gather_agg_f16<__half><<<gather_blocks, 256>>>(aggh, cur, rowptr, esrc, N);

        gemm_f16_pipe<__half><<<gemm_grid, 256, GEMM_SMEM>>>(
            aggh, W1 + (size_t)l * DDIM * DDIM, b1 + (size_t)l * DDIM, hh, N, ntiles);

        if (l == L - 1) {
            gemm_f16_pipe<float><<<gemm_grid, 256, GEMM_SMEM>>>(
                hh, W2 + (size_t)l * DDIM * DDIM, b2 + (size_t)l * DDIM, out, N, ntiles);
        } else {
            __half* dst = (l & 1) ? xh1 : xh0;
            gemm_f16_pipe<__half><<<gemm_grid, 256, GEMM_SMEM>>>(
                hh, W2 + (size_t)l * DDIM * DDIM, b2 + (size_t)l * DDIM, dst, N, ntiles);
            cur = dst;
        }
    }
}